// round 3
// baseline (speedup 1.0000x reference)
#include <cuda_runtime.h>

// topk_mean (k=2) segment pooling.
// h: [BS, SEQ, EMB] fp32, patch_ids: [BS, SEQ] int32 sorted ascending per batch.
// out: [BS, PNUM, EMB] fp32.
// Semantics (faithful to reference tie-masking loop):
//   max1 = segment max; max2 = max over values != max1 (or -1e9 if none)
//   count==0 -> 0 ; count==1 -> max1 ; count>=2 -> (max1 + max2)/2

#define BS   8
#define SEQ  4096
#define EMB  512
#define PNUM 1024
#define NEG_INF_V (-1.0e9f)

// Scratch: starts[b][p] = first token index t with patch_ids[b][t] >= p.
// starts[b][PNUM] = SEQ. No device allocation (enforced) -> __device__ global.
__device__ int g_starts[BS * (PNUM + 1)];

__global__ void starts_kernel(const int* __restrict__ pid) {
    const int b = blockIdx.y;
    const int t = blockIdx.x * blockDim.x + threadIdx.x;
    if (t >= SEQ) return;
    const int* __restrict__ p = pid + b * SEQ;
    int* __restrict__ st = g_starts + b * (PNUM + 1);

    const int cur  = p[t];
    const int prev = (t == 0) ? -1 : p[t - 1];
    // patch ids are sorted: boundary thread fills all skipped patch slots
    for (int q = prev + 1; q <= cur; ++q) st[q] = t;
    if (t == SEQ - 1) {
        for (int q = cur + 1; q <= PNUM; ++q) st[q] = SEQ;
    }
}

__device__ __forceinline__ void top2_update(float v, float& m1, float& m2) {
    // skip v == m1 (reference masks ALL positions equal to max1)
    if (v > m1)      { m2 = m1; m1 = v; }
    else if (v < m1 && v > m2) { m2 = v; }
}

__global__ __launch_bounds__(128)
void pool_kernel(const float4* __restrict__ h4, float4* __restrict__ out4) {
    const int p = blockIdx.x;
    const int b = blockIdx.y;
    const int* __restrict__ st = g_starts + b * (PNUM + 1);
    const int start = st[p];
    const int end   = st[p + 1];
    const int cnt   = end - start;

    float4* __restrict__ o =
        out4 + ((size_t)(b * PNUM + p)) * (EMB / 4) + threadIdx.x;

    if (cnt == 0) {
        *o = make_float4(0.f, 0.f, 0.f, 0.f);
        return;
    }

    const float4* __restrict__ hb =
        h4 + (size_t)b * SEQ * (EMB / 4) + threadIdx.x;

    float4 m1 = hb[(size_t)start * (EMB / 4)];
    if (cnt == 1) {
        *o = m1;
        return;
    }

    float4 m2 = make_float4(-INFINITY, -INFINITY, -INFINITY, -INFINITY);
    for (int t = start + 1; t < end; ++t) {
        const float4 v = hb[(size_t)t * (EMB / 4)];
        top2_update(v.x, m1.x, m2.x);
        top2_update(v.y, m1.y, m2.y);
        top2_update(v.z, m1.z, m2.z);
        top2_update(v.w, m1.w, m2.w);
    }

    float4 r;
    r.x = 0.5f * (m1.x + ((m2.x == -INFINITY) ? NEG_INF_V : m2.x));
    r.y = 0.5f * (m1.y + ((m2.y == -INFINITY) ? NEG_INF_V : m2.y));
    r.z = 0.5f * (m1.z + ((m2.z == -INFINITY) ? NEG_INF_V : m2.z));
    r.w = 0.5f * (m1.w + ((m2.w == -INFINITY) ? NEG_INF_V : m2.w));
    *o = r;
}

extern "C" void kernel_launch(void* const* d_in, const int* in_sizes, int n_in,
                              void* d_out, int out_size) {
    const float* h   = (const float*)d_in[0];
    const int*   pid = (const int*)d_in[1];
    float*       out = (float*)d_out;

    (void)in_sizes; (void)n_in; (void)out_size;

    // Phase 1: segment start offsets from sorted patch_ids
    dim3 g1((SEQ + 255) / 256, BS);
    starts_kernel<<<g1, 256>>>(pid);

    // Phase 2: one CTA per (patch, batch); 128 threads x float4 = 512 dims
    dim3 g2(PNUM, BS);
    pool_kernel<<<g2, 128>>>((const float4*)h, (float4*)out);
}